// round 1
// baseline (speedup 1.0000x reference)
#include <cuda_runtime.h>
#include <cuda_bf16.h>

// LayerProperties: per-channel 4->64->64->3 MLP x2 variants + transmittance epilogue.
// Round 1: correct scalar baseline. One CTA = (channel k, 256 samples).
// Weights for channel k cached in SMEM; h1/h2 in registers, fully unrolled GEMM loops.

#define NCHAN 29
#define HID   64

__device__ __forceinline__ float elu_f(float x) {
    // jax.nn.elu (alpha=1): x if x>0 else exp(x)-1
    return x > 0.0f ? x : (__expf(x) - 1.0f);
}

__device__ __forceinline__ float softplus_f(float x) {
    // stable: max(x,0) + log1p(exp(-|x|))
    return fmaxf(x, 0.0f) + log1pf(__expf(-fabsf(x)));
}

__global__ __launch_bounds__(256) void layer_properties_kernel(
    const float* __restrict__ tau_g,
    const float* __restrict__ tau_lw,
    const float* __restrict__ tau_iw,
    const float* __restrict__ mu,
    const float* __restrict__ mu_bar,
    const float* __restrict__ W1,   // [NC, 4, 64]
    const float* __restrict__ b1,   // [NC, 64]
    const float* __restrict__ W2,   // [NC, 64, 64]
    const float* __restrict__ b2,   // [NC, 64]
    const float* __restrict__ W3,   // [NC, 64, 3]
    const float* __restrict__ b3,   // [NC, 3]
    float* __restrict__ out,        // [B, NC, 8]
    int B)
{
    __shared__ __align__(16) float W1s[4 * HID];
    __shared__ __align__(16) float W2s[HID * HID];
    __shared__ __align__(16) float W3s[HID * 3];
    __shared__ float b1s[HID], b2s[HID], b3s[3];

    const int k   = blockIdx.x;     // channel (fastest grid dim -> L2 reuse of input lines)
    const int tid = threadIdx.x;

    // Stage channel-k weights in SMEM (coalesced global reads).
    for (int i = tid; i < 4 * HID; i += 256)   W1s[i] = W1[k * 4 * HID + i];
    for (int i = tid; i < HID * HID; i += 256) W2s[i] = W2[k * HID * HID + i];
    for (int i = tid; i < HID * 3; i += 256)   W3s[i] = W3[k * HID * 3 + i];
    if (tid < HID) { b1s[tid] = b1[k * HID + tid]; b2s[tid] = b2[k * HID + tid]; }
    if (tid < 3)   { b3s[tid] = b3[k * 3 + tid]; }
    __syncthreads();

    const int b = blockIdx.y * 256 + tid;
    if (b >= B) return;

    const int idx = b * NCHAN + k;
    const float tg = tau_g[idx];
    const float tl = tau_lw[idx];
    const float ti = tau_iw[idx];
    const float m  = mu[b];
    const float mb = mu_bar[b];

    const float tau_tot = tg + tl + ti;

    float* o = out + (size_t)idx * 8;
    // t_direct, t_diffuse
    o[0] = __expf(-tau_tot / (m + 1e-5f));
    o[1] = __expf(-tau_tot / (mb + 1e-3f));

    #pragma unroll 1
    for (int v = 0; v < 2; v++) {
        const float x3 = v ? mb : m;   // direct uses mu, diffuse uses mu_bar

        // ---- layer 1: [4] -> [64], ELU ----
        float h1[HID];
        #pragma unroll
        for (int j = 0; j < HID; j++) {
            float a = fmaf(tg, W1s[j],           b1s[j]);
            a       = fmaf(tl, W1s[HID + j],     a);
            a       = fmaf(ti, W1s[2 * HID + j], a);
            a       = fmaf(x3, W1s[3 * HID + j], a);
            h1[j] = elu_f(a);
        }

        // ---- layer 2: [64] -> [64], ELU ----
        float h2[HID];
        #pragma unroll
        for (int j = 0; j < HID; j++) h2[j] = b2s[j];

        #pragma unroll
        for (int i = 0; i < HID; i++) {
            const float hv = h1[i];
            const float4* w4 = reinterpret_cast<const float4*>(&W2s[i * HID]);
            #pragma unroll
            for (int j4 = 0; j4 < HID / 4; j4++) {
                const float4 w = w4[j4];
                h2[4 * j4 + 0] = fmaf(hv, w.x, h2[4 * j4 + 0]);
                h2[4 * j4 + 1] = fmaf(hv, w.y, h2[4 * j4 + 1]);
                h2[4 * j4 + 2] = fmaf(hv, w.z, h2[4 * j4 + 2]);
                h2[4 * j4 + 3] = fmaf(hv, w.w, h2[4 * j4 + 3]);
            }
        }

        // ---- layer 3: [64] -> [3] (ELU on h2 fused in) ----
        float z0 = b3s[0], z1 = b3s[1], z2 = b3s[2];
        #pragma unroll
        for (int i = 0; i < HID; i++) {
            const float h = elu_f(h2[i]);
            z0 = fmaf(h, W3s[i * 3 + 0], z0);
            z1 = fmaf(h, W3s[i * 3 + 1], z1);
            z2 = fmaf(h, W3s[i * 3 + 2], z2);
        }

        // softplus then softmax over the 3 outputs
        z0 = softplus_f(z0);
        z1 = softplus_f(z1);
        z2 = softplus_f(z2);
        const float zm = fmaxf(z0, fmaxf(z1, z2));
        const float e0 = __expf(z0 - zm);
        const float e1 = __expf(z1 - zm);
        const float e2 = __expf(z2 - zm);
        const float inv = 1.0f / (e0 + e1 + e2);

        o[2 + 3 * v + 0] = e0 * inv;
        o[2 + 3 * v + 1] = e1 * inv;
        o[2 + 3 * v + 2] = e2 * inv;
    }
}

extern "C" void kernel_launch(void* const* d_in, const int* in_sizes, int n_in,
                              void* d_out, int out_size) {
    const float* tau_g  = (const float*)d_in[0];
    const float* tau_lw = (const float*)d_in[1];
    const float* tau_iw = (const float*)d_in[2];
    const float* mu     = (const float*)d_in[3];
    const float* mu_bar = (const float*)d_in[4];
    const float* W1     = (const float*)d_in[5];
    const float* b1     = (const float*)d_in[6];
    const float* W2     = (const float*)d_in[7];
    const float* b2     = (const float*)d_in[8];
    const float* W3     = (const float*)d_in[9];
    const float* b3     = (const float*)d_in[10];
    float* out = (float*)d_out;

    const int B = in_sizes[3];  // mu has B elements

    dim3 grid(NCHAN, (B + 255) / 256);
    dim3 block(256);
    layer_properties_kernel<<<grid, block>>>(tau_g, tau_lw, tau_iw, mu, mu_bar,
                                             W1, b1, W2, b2, W3, b3, out, B);
}

// round 3
// speedup vs baseline: 1.3355x; 1.3355x over previous
#include <cuda_runtime.h>
#include <cuda_bf16.h>
#include <cstdint>

// LayerProperties: per-channel 4->64->64->3 MLP x2 variants + transmittance epilogue.
// Round 2: streaming dataflow (no h1 array -> ~100 regs -> 4 CTAs/SM) +
// packed fma.rn.f32x2 (Blackwell 2xFP32 FMA) for the 64x64 layer.

#define NCHAN 29
#define HID   64

// 64-bit packed f32x2 FMA: d = a*b + c (elementwise on two fp32 lanes)
__device__ __forceinline__ unsigned long long fma2(unsigned long long a,
                                                   unsigned long long b,
                                                   unsigned long long c) {
    unsigned long long d;
    asm("fma.rn.f32x2 %0, %1, %2, %3;" : "=l"(d) : "l"(a), "l"(b), "l"(c));
    return d;
}

__device__ __forceinline__ unsigned long long splat2(float x) {
    unsigned long long d;
    asm("mov.b64 %0, {%1, %1};" : "=l"(d) : "f"(x));
    return d;
}

__device__ __forceinline__ float2 unpack2(unsigned long long p) {
    float lo, hi;
    asm("mov.b64 {%0, %1}, %2;" : "=f"(lo), "=f"(hi) : "l"(p));
    return make_float2(lo, hi);
}

__device__ __forceinline__ float elu_f(float x) {
    return x > 0.0f ? x : (__expf(x) - 1.0f);
}

__device__ __forceinline__ float softplus_f(float x) {
    return fmaxf(x, 0.0f) + log1pf(__expf(-fabsf(x)));
}

__global__ __launch_bounds__(128, 4) void layer_properties_kernel(
    const float* __restrict__ tau_g,
    const float* __restrict__ tau_lw,
    const float* __restrict__ tau_iw,
    const float* __restrict__ mu,
    const float* __restrict__ mu_bar,
    const float* __restrict__ W1,   // [NC, 4, 64]
    const float* __restrict__ b1,   // [NC, 64]
    const float* __restrict__ W2,   // [NC, 64, 64]
    const float* __restrict__ b2,   // [NC, 64]
    const float* __restrict__ W3,   // [NC, 64, 3]
    const float* __restrict__ b3,   // [NC, 3]
    float* __restrict__ out,        // [B, NC, 8]
    int B)
{
    __shared__ __align__(16) float W1s[4 * HID];
    __shared__ __align__(16) float W2s[HID * HID];
    __shared__ __align__(16) float W3s[HID * 3];
    __shared__ float b1s[HID], b2s[HID], b3s[3];

    const int k   = blockIdx.x;     // channel fastest -> L2 reuse across channels of a b-tile
    const int tid = threadIdx.x;

    for (int i = tid; i < 4 * HID; i += 128)   W1s[i] = W1[k * 4 * HID + i];
    for (int i = tid; i < HID * HID; i += 128) W2s[i] = W2[k * HID * HID + i];
    for (int i = tid; i < HID * 3; i += 128)   W3s[i] = W3[k * HID * 3 + i];
    if (tid < HID) { b1s[tid] = b1[k * HID + tid]; b2s[tid] = b2[k * HID + tid]; }
    if (tid < 3)   { b3s[tid] = b3[k * 3 + tid]; }
    __syncthreads();

    const int b = blockIdx.y * 128 + tid;
    if (b >= B) return;

    const int idx = b * NCHAN + k;
    const float tg = tau_g[idx];
    const float tl = tau_lw[idx];
    const float ti = tau_iw[idx];
    const float m  = mu[b];
    const float mb = mu_bar[b];

    const float tau_tot = tg + tl + ti;

    float res[8];
    res[0] = __expf(-tau_tot / (m + 1e-5f));
    res[1] = __expf(-tau_tot / (mb + 1e-3f));

    #pragma unroll 1
    for (int v = 0; v < 2; v++) {
        const float x3 = v ? mb : m;

        // h2 accumulators: 32 packed f32x2 pairs, init from b2
        unsigned long long h2p[HID / 2];
        {
            const unsigned long long* b2p = reinterpret_cast<const unsigned long long*>(b2s);
            #pragma unroll
            for (int j = 0; j < HID / 2; j++) h2p[j] = b2p[j];
        }

        // Streamed layer1 -> rank-1 update of layer2 (h1[i] never stored)
        #pragma unroll 4
        for (int i = 0; i < HID; i++) {
            float a = fmaf(tg, W1s[i],           b1s[i]);
            a       = fmaf(tl, W1s[HID + i],     a);
            a       = fmaf(ti, W1s[2 * HID + i], a);
            a       = fmaf(x3, W1s[3 * HID + i], a);
            const unsigned long long hh = splat2(elu_f(a));

            const ulonglong2* w2 = reinterpret_cast<const ulonglong2*>(&W2s[i * HID]);
            #pragma unroll
            for (int j4 = 0; j4 < HID / 4; j4++) {
                const ulonglong2 w = w2[j4];   // LDS.128: two f32x2 pairs
                h2p[2 * j4 + 0] = fma2(hh, w.x, h2p[2 * j4 + 0]);
                h2p[2 * j4 + 1] = fma2(hh, w.y, h2p[2 * j4 + 1]);
            }
        }

        // Layer 3: ELU(h2) dot W3 -> 3 logits (streamed over h2 pairs)
        float z0 = b3s[0], z1 = b3s[1], z2 = b3s[2];
        #pragma unroll
        for (int j = 0; j < HID / 2; j++) {
            const float2 hp = unpack2(h2p[j]);
            const float ha = elu_f(hp.x);
            const float hb = elu_f(hp.y);
            const int i0 = 2 * j, i1 = 2 * j + 1;
            z0 = fmaf(ha, W3s[i0 * 3 + 0], z0);
            z1 = fmaf(ha, W3s[i0 * 3 + 1], z1);
            z2 = fmaf(ha, W3s[i0 * 3 + 2], z2);
            z0 = fmaf(hb, W3s[i1 * 3 + 0], z0);
            z1 = fmaf(hb, W3s[i1 * 3 + 1], z1);
            z2 = fmaf(hb, W3s[i1 * 3 + 2], z2);
        }

        z0 = softplus_f(z0);
        z1 = softplus_f(z1);
        z2 = softplus_f(z2);
        const float zm = fmaxf(z0, fmaxf(z1, z2));
        const float e0 = __expf(z0 - zm);
        const float e1 = __expf(z1 - zm);
        const float e2 = __expf(z2 - zm);
        const float inv = 1.0f / (e0 + e1 + e2);

        res[2 + 3 * v + 0] = e0 * inv;
        res[2 + 3 * v + 1] = e1 * inv;
        res[2 + 3 * v + 2] = e2 * inv;
    }

    // Two coalesced 16B stores per sample-channel
    float4* o4 = reinterpret_cast<float4*>(out + (size_t)idx * 8);
    o4[0] = make_float4(res[0], res[1], res[2], res[3]);
    o4[1] = make_float4(res[4], res[5], res[6], res[7]);
}

extern "C" void kernel_launch(void* const* d_in, const int* in_sizes, int n_in,
                              void* d_out, int out_size) {
    const float* tau_g  = (const float*)d_in[0];
    const float* tau_lw = (const float*)d_in[1];
    const float* tau_iw = (const float*)d_in[2];
    const float* mu     = (const float*)d_in[3];
    const float* mu_bar = (const float*)d_in[4];
    const float* W1     = (const float*)d_in[5];
    const float* b1     = (const float*)d_in[6];
    const float* W2     = (const float*)d_in[7];
    const float* b2     = (const float*)d_in[8];
    const float* W3     = (const float*)d_in[9];
    const float* b3     = (const float*)d_in[10];
    float* out = (float*)d_out;

    const int B = in_sizes[3];  // mu has B elements

    dim3 grid(NCHAN, (B + 127) / 128);
    dim3 block(128);
    layer_properties_kernel<<<grid, block>>>(tau_g, tau_lw, tau_iw, mu, mu_bar,
                                             W1, b1, W2, b2, W3, b3, out, B);
}

// round 4
// speedup vs baseline: 2.1132x; 1.5823x over previous
#include <cuda_runtime.h>
#include <cuda_bf16.h>
#include <cstdint>

// LayerProperties: per-channel 4->64->64->3 MLP x2 variants + transmittance epilogue.
// Round 3: FUSE the direct/diffuse variants over a single W2 sweep.
//  - W2 row read once per i serves both variants (halves broadcast LDS traffic,
//    which ncu showed at 83.5% of L1/shared throughput).
//  - Layer-1 partial sum (tg,tl,ti terms) shared between variants: 6 FFMA not 8.
//  - W1 transposed to [64][4] float4, W3 padded to [64][4] float4: 1 LDS.128 each.
//  - Packed fma.rn.f32x2 for all 64x64 MACs.

#define NCHAN 29
#define HID   64

typedef unsigned long long ull;

__device__ __forceinline__ ull fma2(ull a, ull b, ull c) {
    ull d;
    asm("fma.rn.f32x2 %0, %1, %2, %3;" : "=l"(d) : "l"(a), "l"(b), "l"(c));
    return d;
}

__device__ __forceinline__ ull splat2(float x) {
    ull d;
    asm("mov.b64 %0, {%1, %1};" : "=l"(d) : "f"(x));
    return d;
}

__device__ __forceinline__ float2 unpack2(ull p) {
    float lo, hi;
    asm("mov.b64 {%0, %1}, %2;" : "=f"(lo), "=f"(hi) : "l"(p));
    return make_float2(lo, hi);
}

__device__ __forceinline__ float elu_f(float x) {
    return x > 0.0f ? x : (__expf(x) - 1.0f);
}

__device__ __forceinline__ float softplus_f(float x) {
    return fmaxf(x, 0.0f) + log1pf(__expf(-fabsf(x)));
}

__global__ __launch_bounds__(128, 2) void layer_properties_kernel(
    const float* __restrict__ tau_g,
    const float* __restrict__ tau_lw,
    const float* __restrict__ tau_iw,
    const float* __restrict__ mu,
    const float* __restrict__ mu_bar,
    const float* __restrict__ W1,   // [NC, 4, 64]
    const float* __restrict__ b1,   // [NC, 64]
    const float* __restrict__ W2,   // [NC, 64, 64]
    const float* __restrict__ b2,   // [NC, 64]
    const float* __restrict__ W3,   // [NC, 64, 3]
    const float* __restrict__ b3,   // [NC, 3]
    float* __restrict__ out,        // [B, NC, 8]
    int B)
{
    __shared__ __align__(16) float4 W1Ts[HID];      // (W1[0][i],W1[1][i],W1[2][i],W1[3][i])
    __shared__ __align__(16) float  W2s[HID * HID]; // row-major [i][j]
    __shared__ __align__(16) float4 W3Ts[HID];      // (W3[i][0],W3[i][1],W3[i][2],0)
    __shared__ float b1s[HID], b2s[HID], b3s[3];

    const int k   = blockIdx.x;     // channel fastest -> L2 reuse across channels of a b-tile
    const int tid = threadIdx.x;

    // ---- stage channel-k weights ----
    {
        const float4* W2g = reinterpret_cast<const float4*>(W2 + (size_t)k * HID * HID);
        float4* W2s4 = reinterpret_cast<float4*>(W2s);
        #pragma unroll
        for (int i = 0; i < (HID * HID / 4) / 128; i++)
            W2s4[i * 128 + tid] = W2g[i * 128 + tid];

        if (tid < HID) {
            const float* w1g = W1 + (size_t)k * 4 * HID;
            W1Ts[tid] = make_float4(w1g[tid], w1g[HID + tid], w1g[2 * HID + tid], w1g[3 * HID + tid]);
            const float* w3g = W3 + (size_t)k * HID * 3;
            W3Ts[tid] = make_float4(w3g[tid * 3 + 0], w3g[tid * 3 + 1], w3g[tid * 3 + 2], 0.0f);
            b1s[tid] = b1[k * HID + tid];
            b2s[tid] = b2[k * HID + tid];
        }
        if (tid < 3) b3s[tid] = b3[k * 3 + tid];
    }
    __syncthreads();

    const int b = blockIdx.y * 128 + tid;
    if (b >= B) return;

    const int idx = b * NCHAN + k;
    const float tg = tau_g[idx];
    const float tl = tau_lw[idx];
    const float ti = tau_iw[idx];
    const float m  = mu[b];
    const float mb = mu_bar[b];

    // ---- layer 2 accumulators for BOTH variants (packed f32x2 pairs) ----
    ull accD[HID / 2], accF[HID / 2];
    {
        const ull* b2p = reinterpret_cast<const ull*>(b2s);
        #pragma unroll
        for (int j = 0; j < HID / 2; j++) { accD[j] = b2p[j]; accF[j] = b2p[j]; }
    }

    // ---- fused layer1 -> rank-1 updates, single W2 sweep ----
    #pragma unroll 4
    for (int i = 0; i < HID; i++) {
        const float4 w1 = W1Ts[i];
        float s = fmaf(tg, w1.x, b1s[i]);
        s       = fmaf(tl, w1.y, s);
        s       = fmaf(ti, w1.z, s);
        const float ad = fmaf(m,  w1.w, s);
        const float af = fmaf(mb, w1.w, s);
        const ull hd = splat2(elu_f(ad));
        const ull hf = splat2(elu_f(af));

        const ulonglong2* w2 = reinterpret_cast<const ulonglong2*>(&W2s[i * HID]);
        #pragma unroll
        for (int j = 0; j < HID / 4; j++) {
            const ulonglong2 w = w2[j];   // one LDS.128 = 4 weights (2 packed pairs)
            accD[2 * j + 0] = fma2(hd, w.x, accD[2 * j + 0]);
            accD[2 * j + 1] = fma2(hd, w.y, accD[2 * j + 1]);
            accF[2 * j + 0] = fma2(hf, w.x, accF[2 * j + 0]);
            accF[2 * j + 1] = fma2(hf, w.y, accF[2 * j + 1]);
        }
    }

    // ---- fused layer 3: ELU(h2) . W3 for both variants, W3 read once ----
    float zd0 = b3s[0], zd1 = b3s[1], zd2 = b3s[2];
    float zf0 = zd0,    zf1 = zd1,    zf2 = zd2;
    #pragma unroll
    for (int j = 0; j < HID / 2; j++) {
        const float4 w3a = W3Ts[2 * j + 0];
        const float4 w3b = W3Ts[2 * j + 1];
        const float2 hdp = unpack2(accD[j]);
        const float2 hfp = unpack2(accF[j]);
        const float hd0 = elu_f(hdp.x), hd1 = elu_f(hdp.y);
        const float hf0 = elu_f(hfp.x), hf1 = elu_f(hfp.y);
        zd0 = fmaf(hd0, w3a.x, zd0); zd1 = fmaf(hd0, w3a.y, zd1); zd2 = fmaf(hd0, w3a.z, zd2);
        zd0 = fmaf(hd1, w3b.x, zd0); zd1 = fmaf(hd1, w3b.y, zd1); zd2 = fmaf(hd1, w3b.z, zd2);
        zf0 = fmaf(hf0, w3a.x, zf0); zf1 = fmaf(hf0, w3a.y, zf1); zf2 = fmaf(hf0, w3a.z, zf2);
        zf0 = fmaf(hf1, w3b.x, zf0); zf1 = fmaf(hf1, w3b.y, zf1); zf2 = fmaf(hf1, w3b.z, zf2);
    }

    // ---- epilogue: transmittances + softplus+softmax per variant ----
    const float tau_tot = tg + tl + ti;
    const float t_dir = __expf(-tau_tot / (m  + 1e-5f));
    const float t_dif = __expf(-tau_tot / (mb + 1e-3f));

    zd0 = softplus_f(zd0); zd1 = softplus_f(zd1); zd2 = softplus_f(zd2);
    float zm = fmaxf(zd0, fmaxf(zd1, zd2));
    float e0 = __expf(zd0 - zm), e1 = __expf(zd1 - zm), e2 = __expf(zd2 - zm);
    float inv = 1.0f / (e0 + e1 + e2);
    const float d0 = e0 * inv, d1 = e1 * inv, d2 = e2 * inv;

    zf0 = softplus_f(zf0); zf1 = softplus_f(zf1); zf2 = softplus_f(zf2);
    zm = fmaxf(zf0, fmaxf(zf1, zf2));
    e0 = __expf(zf0 - zm); e1 = __expf(zf1 - zm); e2 = __expf(zf2 - zm);
    inv = 1.0f / (e0 + e1 + e2);
    const float f0 = e0 * inv, f1 = e1 * inv, f2 = e2 * inv;

    float4* o4 = reinterpret_cast<float4*>(out + (size_t)idx * 8);
    o4[0] = make_float4(t_dir, t_dif, d0, d1);
    o4[1] = make_float4(d2, f0, f1, f2);
}

extern "C" void kernel_launch(void* const* d_in, const int* in_sizes, int n_in,
                              void* d_out, int out_size) {
    const float* tau_g  = (const float*)d_in[0];
    const float* tau_lw = (const float*)d_in[1];
    const float* tau_iw = (const float*)d_in[2];
    const float* mu     = (const float*)d_in[3];
    const float* mu_bar = (const float*)d_in[4];
    const float* W1     = (const float*)d_in[5];
    const float* b1     = (const float*)d_in[6];
    const float* W2     = (const float*)d_in[7];
    const float* b2     = (const float*)d_in[8];
    const float* W3     = (const float*)d_in[9];
    const float* b3     = (const float*)d_in[10];
    float* out = (float*)d_out;

    const int B = in_sizes[3];  // mu has B elements

    dim3 grid(NCHAN, (B + 127) / 128);
    dim3 block(128);
    layer_properties_kernel<<<grid, block>>>(tau_g, tau_lw, tau_iw, mu, mu_bar,
                                             W1, b1, W2, b2, W3, b3, out, B);
}

// round 6
// speedup vs baseline: 2.5884x; 1.2249x over previous
#include <cuda_runtime.h>
#include <cuda_bf16.h>
#include <cstdint>

// LayerProperties: per-channel 4->64->64->3 MLP x2 variants + epilogue.
// Round 5: layer-2 on tensor cores via plain mma.sync (m16n8k16 bf16, HMMA path,
// compiles on compute_103 target). bf16 2-term split: D = Ahi*Bhi + Ahi*Blo + Alo*Bhi.
// CTA = (channel, 128 samples). SMEM row stride 72 bf16 (36 words) makes all
// fragment LDS.32 loads bank-conflict-free (4g+c mapping).

#define NCHAN 29
#define HID   64
#define STR   72            // bf16 elems per staged row (36 words, 144 B)

// ---- SMEM byte offsets (dynamic) ----
#define OFF_AHI  0
#define OFF_ALO  18432
#define OFF_BHI  36864
#define OFF_BLO  46080
#define OFF_W1T  55296
#define OFF_W3T  56320
#define OFF_B1   57344
#define OFF_B2   57600
#define OFF_B3   57856
#define OFF_OUTS 57872
#define SMEM_TOTAL 61968

__device__ __forceinline__ float elu_f(float x) {
    return x > 0.0f ? x : (__expf(x) - 1.0f);
}
__device__ __forceinline__ float softplus_f(float x) {
    return fmaxf(x, 0.0f) + log1pf(__expf(-fabsf(x)));
}

__device__ __forceinline__ void mma_bf16(float d[4],
                                         uint32_t a0, uint32_t a1, uint32_t a2, uint32_t a3,
                                         uint32_t b0, uint32_t b1) {
    asm volatile(
        "mma.sync.aligned.m16n8k16.row.col.f32.bf16.bf16.f32 "
        "{%0,%1,%2,%3}, {%4,%5,%6,%7}, {%8,%9}, {%0,%1,%2,%3};"
        : "+f"(d[0]), "+f"(d[1]), "+f"(d[2]), "+f"(d[3])
        : "r"(a0), "r"(a1), "r"(a2), "r"(a3), "r"(b0), "r"(b1));
}

__device__ __forceinline__ uint32_t pack_bf16(__nv_bfloat16 lo, __nv_bfloat16 hi) {
    return (uint32_t)__bfloat16_as_ushort(lo) | ((uint32_t)__bfloat16_as_ushort(hi) << 16);
}

__global__ __launch_bounds__(128, 3) void mlp_kernel(
    const float* __restrict__ tau_g,
    const float* __restrict__ tau_lw,
    const float* __restrict__ tau_iw,
    const float* __restrict__ mu,
    const float* __restrict__ mu_bar,
    const float* __restrict__ W1,   // [NC, 4, 64]
    const float* __restrict__ b1,   // [NC, 64]
    const float* __restrict__ W2,   // [NC, 64, 64]  (W2[i][n]: i=input, n=output)
    const float* __restrict__ b2,   // [NC, 64]
    const float* __restrict__ W3,   // [NC, 64, 3]
    const float* __restrict__ b3,   // [NC, 3]
    float* __restrict__ out,        // [B, NC, 8]
    int B)
{
    extern __shared__ __align__(16) unsigned char sm[];
    uint32_t* AHI32 = reinterpret_cast<uint32_t*>(sm + OFF_AHI);   // [128 rows][36 words]
    uint32_t* ALO32 = reinterpret_cast<uint32_t*>(sm + OFF_ALO);
    uint32_t* BHI32 = reinterpret_cast<uint32_t*>(sm + OFF_BHI);   // [64 n-rows][36 words]
    uint32_t* BLO32 = reinterpret_cast<uint32_t*>(sm + OFF_BLO);
    __nv_bfloat16* BHIe = reinterpret_cast<__nv_bfloat16*>(sm + OFF_BHI);
    __nv_bfloat16* BLOe = reinterpret_cast<__nv_bfloat16*>(sm + OFF_BLO);
    float4* W1Ts = reinterpret_cast<float4*>(sm + OFF_W1T);
    float4* W3Ts = reinterpret_cast<float4*>(sm + OFF_W3T);
    float* b1s = reinterpret_cast<float*>(sm + OFF_B1);
    float* b2s = reinterpret_cast<float*>(sm + OFF_B2);
    float* b3s = reinterpret_cast<float*>(sm + OFF_B3);
    float* outS = reinterpret_cast<float*>(sm + OFF_OUTS);         // [128][8]

    const int tid  = threadIdx.x;
    const int wid  = tid >> 5;
    const int lane = tid & 31;
    const int k    = blockIdx.x;

    // ---- stage W2 split transposed: B image row n holds W2[.][n] over i (K-contig) ----
    for (int idx = tid; idx < HID * HID; idx += 128) {
        const int i = idx >> 6;          // input index (K dim)
        const int n = idx & 63;          // output neuron (N dim)
        const float w = W2[(size_t)k * HID * HID + idx];
        const __nv_bfloat16 hi = __float2bfloat16(w);
        const __nv_bfloat16 lo = __float2bfloat16(w - __bfloat162float(hi));
        BHIe[n * STR + i] = hi;
        BLOe[n * STR + i] = lo;
    }
    if (tid < HID) {
        const float* w1g = W1 + (size_t)k * 4 * HID;
        W1Ts[tid] = make_float4(w1g[tid], w1g[HID + tid], w1g[2 * HID + tid], w1g[3 * HID + tid]);
        const float* w3g = W3 + (size_t)k * HID * 3;
        W3Ts[tid] = make_float4(w3g[tid * 3 + 0], w3g[tid * 3 + 1], w3g[tid * 3 + 2], 0.0f);
        b1s[tid] = b1[k * HID + tid];
        b2s[tid] = b2[k * HID + tid];
    }
    if (tid < 3) b3s[tid] = b3[k * 3 + tid];
    __syncthreads();

    // ---- per-thread sample inputs ----
    const int b_raw = blockIdx.y * 128 + tid;
    const int b = (b_raw < B) ? b_raw : (B - 1);
    const int idx_in = b * NCHAN + k;
    const float tg = tau_g[idx_in];
    const float tl = tau_lw[idx_in];
    const float ti = tau_iw[idx_in];
    const float m  = mu[b];
    const float mb = mu_bar[b];

    {
        const float tau_tot = tg + tl + ti;
        outS[tid * 8 + 0] = __expf(-tau_tot / (m + 1e-5f));
        outS[tid * 8 + 1] = __expf(-tau_tot / (mb + 1e-3f));
    }

    const int g  = lane >> 2;        // fragment group row 0..7
    const int cq = lane & 3;         // quad col index 0..3

    #pragma unroll 1
    for (int v = 0; v < 2; v++) {
        const float x3 = v ? mb : m;

        // ---- layer 1 for this thread's sample; bf16 split; stage row tid ----
        #pragma unroll
        for (int c = 0; c < 32; c++) {
            const float4 wa = W1Ts[2 * c];
            const float4 wb = W1Ts[2 * c + 1];
            float s0 = fmaf(tg, wa.x, b1s[2 * c]);
            s0 = fmaf(tl, wa.y, s0); s0 = fmaf(ti, wa.z, s0); s0 = fmaf(x3, wa.w, s0);
            float s1 = fmaf(tg, wb.x, b1s[2 * c + 1]);
            s1 = fmaf(tl, wb.y, s1); s1 = fmaf(ti, wb.z, s1); s1 = fmaf(x3, wb.w, s1);
            const float h0 = elu_f(s0);
            const float h1 = elu_f(s1);
            const __nv_bfloat16 h0h = __float2bfloat16(h0);
            const __nv_bfloat16 h1h = __float2bfloat16(h1);
            const __nv_bfloat16 h0l = __float2bfloat16(h0 - __bfloat162float(h0h));
            const __nv_bfloat16 h1l = __float2bfloat16(h1 - __bfloat162float(h1h));
            AHI32[tid * 36 + c] = pack_bf16(h0h, h1h);
            ALO32[tid * 36 + c] = pack_bf16(h0l, h1l);
        }
        __syncthreads();

        // ---- mma: warp computes rows [wid*32, wid*32+32), all 64 cols ----
        float acc[2][8][4];
        #pragma unroll
        for (int mt = 0; mt < 2; mt++)
            #pragma unroll
            for (int nt = 0; nt < 8; nt++) {
                const float cA = b2s[nt * 8 + cq * 2];
                const float cB = b2s[nt * 8 + cq * 2 + 1];
                acc[mt][nt][0] = cA; acc[mt][nt][1] = cB;
                acc[mt][nt][2] = cA; acc[mt][nt][3] = cB;
            }

        #pragma unroll
        for (int ks = 0; ks < 4; ks++) {
            uint32_t AH[2][4], AL[2][4];
            #pragma unroll
            for (int mt = 0; mt < 2; mt++) {
                const int r0 = wid * 32 + mt * 16 + g;
                const int w0 = r0 * 36 + ks * 8 + cq;
                const int w1 = (r0 + 8) * 36 + ks * 8 + cq;
                AH[mt][0] = AHI32[w0];     AH[mt][1] = AHI32[w1];
                AH[mt][2] = AHI32[w0 + 4]; AH[mt][3] = AHI32[w1 + 4];
                AL[mt][0] = ALO32[w0];     AL[mt][1] = ALO32[w1];
                AL[mt][2] = ALO32[w0 + 4]; AL[mt][3] = ALO32[w1 + 4];
            }
            #pragma unroll
            for (int nt = 0; nt < 8; nt++) {
                const int n = nt * 8 + g;
                const int wb0 = n * 36 + ks * 8 + cq;
                const uint32_t BH0 = BHI32[wb0], BH1 = BHI32[wb0 + 4];
                const uint32_t BL0 = BLO32[wb0], BL1 = BLO32[wb0 + 4];
                #pragma unroll
                for (int mt = 0; mt < 2; mt++) {
                    mma_bf16(acc[mt][nt], AH[mt][0], AH[mt][1], AH[mt][2], AH[mt][3], BH0, BH1);
                    mma_bf16(acc[mt][nt], AH[mt][0], AH[mt][1], AH[mt][2], AH[mt][3], BL0, BL1);
                    mma_bf16(acc[mt][nt], AL[mt][0], AL[mt][1], AL[mt][2], AL[mt][3], BH0, BH1);
                }
            }
        }
        __syncthreads();   // h1 staging buffers free for next variant

        // ---- epilogue: ELU(h2) . W3, quad reduction, softplus+softmax ----
        #pragma unroll
        for (int mt = 0; mt < 2; mt++) {
            float zA0 = 0.f, zA1 = 0.f, zA2 = 0.f;   // row g
            float zB0 = 0.f, zB1 = 0.f, zB2 = 0.f;   // row g+8
            #pragma unroll
            for (int nt = 0; nt < 8; nt++) {
                const int col = nt * 8 + cq * 2;
                const float4 w3a = W3Ts[col];
                const float4 w3b = W3Ts[col + 1];
                const float h00 = elu_f(acc[mt][nt][0]);
                const float h01 = elu_f(acc[mt][nt][1]);
                const float h10 = elu_f(acc[mt][nt][2]);
                const float h11 = elu_f(acc[mt][nt][3]);
                zA0 = fmaf(h00, w3a.x, zA0); zA0 = fmaf(h01, w3b.x, zA0);
                zA1 = fmaf(h00, w3a.y, zA1); zA1 = fmaf(h01, w3b.y, zA1);
                zA2 = fmaf(h00, w3a.z, zA2); zA2 = fmaf(h01, w3b.z, zA2);
                zB0 = fmaf(h10, w3a.x, zB0); zB0 = fmaf(h11, w3b.x, zB0);
                zB1 = fmaf(h10, w3a.y, zB1); zB1 = fmaf(h11, w3b.y, zB1);
                zB2 = fmaf(h10, w3a.z, zB2); zB2 = fmaf(h11, w3b.z, zB2);
            }
            // reduce over the 4 quad lanes (same row, different cols)
            zA0 += __shfl_xor_sync(0xffffffffu, zA0, 1); zA0 += __shfl_xor_sync(0xffffffffu, zA0, 2);
            zA1 += __shfl_xor_sync(0xffffffffu, zA1, 1); zA1 += __shfl_xor_sync(0xffffffffu, zA1, 2);
            zA2 += __shfl_xor_sync(0xffffffffu, zA2, 1); zA2 += __shfl_xor_sync(0xffffffffu, zA2, 2);
            zB0 += __shfl_xor_sync(0xffffffffu, zB0, 1); zB0 += __shfl_xor_sync(0xffffffffu, zB0, 2);
            zB1 += __shfl_xor_sync(0xffffffffu, zB1, 1); zB1 += __shfl_xor_sync(0xffffffffu, zB1, 2);
            zB2 += __shfl_xor_sync(0xffffffffu, zB2, 1); zB2 += __shfl_xor_sync(0xffffffffu, zB2, 2);

            if (cq == 0) {
                {
                    float z0 = softplus_f(zA0 + b3s[0]);
                    float z1 = softplus_f(zA1 + b3s[1]);
                    float z2 = softplus_f(zA2 + b3s[2]);
                    const float zm = fmaxf(z0, fmaxf(z1, z2));
                    const float e0 = __expf(z0 - zm), e1 = __expf(z1 - zm), e2 = __expf(z2 - zm);
                    const float inv = 1.0f / (e0 + e1 + e2);
                    const int row = wid * 32 + mt * 16 + g;
                    outS[row * 8 + 2 + 3 * v + 0] = e0 * inv;
                    outS[row * 8 + 2 + 3 * v + 1] = e1 * inv;
                    outS[row * 8 + 2 + 3 * v + 2] = e2 * inv;
                }
                {
                    float z0 = softplus_f(zB0 + b3s[0]);
                    float z1 = softplus_f(zB1 + b3s[1]);
                    float z2 = softplus_f(zB2 + b3s[2]);
                    const float zm = fmaxf(z0, fmaxf(z1, z2));
                    const float e0 = __expf(z0 - zm), e1 = __expf(z1 - zm), e2 = __expf(z2 - zm);
                    const float inv = 1.0f / (e0 + e1 + e2);
                    const int row = wid * 32 + mt * 16 + g + 8;
                    outS[row * 8 + 2 + 3 * v + 0] = e0 * inv;
                    outS[row * 8 + 2 + 3 * v + 1] = e1 * inv;
                    outS[row * 8 + 2 + 3 * v + 2] = e2 * inv;
                }
            }
        }
    }

    __syncthreads();
    if (b_raw < B) {
        const float4* s4 = reinterpret_cast<const float4*>(&outS[tid * 8]);
        float4* o4 = reinterpret_cast<float4*>(out + (size_t)idx_in * 8);
        o4[0] = s4[0];
        o4[1] = s4[1];
    }
}

extern "C" void kernel_launch(void* const* d_in, const int* in_sizes, int n_in,
                              void* d_out, int out_size) {
    const float* tau_g  = (const float*)d_in[0];
    const float* tau_lw = (const float*)d_in[1];
    const float* tau_iw = (const float*)d_in[2];
    const float* mu     = (const float*)d_in[3];
    const float* mu_bar = (const float*)d_in[4];
    const float* W1     = (const float*)d_in[5];
    const float* b1     = (const float*)d_in[6];
    const float* W2     = (const float*)d_in[7];
    const float* b2     = (const float*)d_in[8];
    const float* W3     = (const float*)d_in[9];
    const float* b3     = (const float*)d_in[10];
    float* out = (float*)d_out;

    const int B = in_sizes[3];  // mu has B elements

    cudaFuncSetAttribute(mlp_kernel, cudaFuncAttributeMaxDynamicSharedMemorySize, SMEM_TOTAL);

    dim3 grid(NCHAN, (B + 127) / 128);
    mlp_kernel<<<grid, 128, SMEM_TOTAL>>>(tau_g, tau_lw, tau_iw, mu, mu_bar,
                                          W1, b1, W2, b2, W3, b3, out, B);
}

// round 8
// speedup vs baseline: 2.7657x; 1.0685x over previous
#include <cuda_runtime.h>
#include <cuda_bf16.h>
#include <cstdint>

// LayerProperties: per-channel 4->64->64->3 MLP x2 variants + epilogue.
// Round 6: issue-count + occupancy attack on the Round-5 mma.sync kernel.
//  - producer h1 staging via STS.128 (conflict-free), was 4-way-conflicted STS.32
//  - B (W2 split) staged once per CTA in *fragment order* -> consumer LDS.64
//  - outS buffer dropped (direct global stores) -> smem 54.6KB -> 4 CTAs/SM
//  - __launch_bounds__(128,4); 3-term bf16 split D = Ahi*Bhi + Ahi*Blo + Alo*Bhi

#define NCHAN 29
#define HID   64

// ---- SMEM byte offsets (dynamic) ----
#define OFF_AHI  0          // [128 rows][36 words]  (row stride 144 B)
#define OFF_ALO  18432
#define OFF_BFH  36864      // fragment order: [ks=4][nt=8][lane=32] uint2 = 8 KB
#define OFF_BFL  45056
#define OFF_W1T  53248      // float4[64]
#define OFF_W3T  54272      // float4[64]
#define OFF_B1   55296
#define OFF_B2   55552
#define OFF_B3   55808
#define SMEM_TOTAL 55840

__device__ __forceinline__ float elu_f(float x) {
    return x > 0.0f ? x : (__expf(x) - 1.0f);
}
__device__ __forceinline__ float softplus_f(float x) {
    return fmaxf(x, 0.0f) + log1pf(__expf(-fabsf(x)));
}

__device__ __forceinline__ void mma_bf16(float d[4],
                                         uint32_t a0, uint32_t a1, uint32_t a2, uint32_t a3,
                                         uint32_t b0, uint32_t b1) {
    asm volatile(
        "mma.sync.aligned.m16n8k16.row.col.f32.bf16.bf16.f32 "
        "{%0,%1,%2,%3}, {%4,%5,%6,%7}, {%8,%9}, {%0,%1,%2,%3};"
        : "+f"(d[0]), "+f"(d[1]), "+f"(d[2]), "+f"(d[3])
        : "r"(a0), "r"(a1), "r"(a2), "r"(a3), "r"(b0), "r"(b1));
}

__device__ __forceinline__ uint32_t pack_bf16(__nv_bfloat16 lo, __nv_bfloat16 hi) {
    return (uint32_t)__bfloat16_as_ushort(lo) | ((uint32_t)__bfloat16_as_ushort(hi) << 16);
}

__global__ __launch_bounds__(128, 4) void mlp_kernel(
    const float* __restrict__ tau_g,
    const float* __restrict__ tau_lw,
    const float* __restrict__ tau_iw,
    const float* __restrict__ mu,
    const float* __restrict__ mu_bar,
    const float* __restrict__ W1,   // [NC, 4, 64]
    const float* __restrict__ b1,   // [NC, 64]
    const float* __restrict__ W2,   // [NC, 64, 64]  (W2[i][n]: i=input, n=output)
    const float* __restrict__ b2,   // [NC, 64]
    const float* __restrict__ W3,   // [NC, 64, 3]
    const float* __restrict__ b3,   // [NC, 3]
    float* __restrict__ out,        // [B, NC, 8]
    int B)
{
    extern __shared__ __align__(16) unsigned char sm[];
    uint32_t* AHI32 = reinterpret_cast<uint32_t*>(sm + OFF_AHI);
    uint32_t* ALO32 = reinterpret_cast<uint32_t*>(sm + OFF_ALO);
    uint2* BFH = reinterpret_cast<uint2*>(sm + OFF_BFH);
    uint2* BFL = reinterpret_cast<uint2*>(sm + OFF_BFL);
    float4* W1Ts = reinterpret_cast<float4*>(sm + OFF_W1T);
    float4* W3Ts = reinterpret_cast<float4*>(sm + OFF_W3T);
    float* b1s = reinterpret_cast<float*>(sm + OFF_B1);
    float* b2s = reinterpret_cast<float*>(sm + OFF_B2);
    float* b3s = reinterpret_cast<float*>(sm + OFF_B3);

    const int tid  = threadIdx.x;
    const int wid  = tid >> 5;
    const int lane = tid & 31;
    const int k    = blockIdx.x;

    // ---- stage B (W2 split) in fragment order, once per CTA ----
    // entry e = (ks*8+nt)*32 + lane; thread handles e = tid, tid+128, ...
    {
        const float* W2g = W2 + (size_t)k * HID * HID;
        #pragma unroll
        for (int rep = 0; rep < 8; rep++) {
            const int e  = rep * 128 + tid;
            const int el = e & 31;            // lane slot
            const int nt = (e >> 5) & 7;
            const int ks = e >> 8;            // 0..3
            const int g  = el >> 2;
            const int cq = el & 3;
            const int n  = nt * 8 + g;
            const int k0 = ks * 16 + cq * 2;
            float w00 = W2g[(k0 + 0) * HID + n];
            float w01 = W2g[(k0 + 1) * HID + n];
            float w10 = W2g[(k0 + 8) * HID + n];
            float w11 = W2g[(k0 + 9) * HID + n];
            __nv_bfloat16 h00 = __float2bfloat16(w00);
            __nv_bfloat16 h01 = __float2bfloat16(w01);
            __nv_bfloat16 h10 = __float2bfloat16(w10);
            __nv_bfloat16 h11 = __float2bfloat16(w11);
            BFH[e] = make_uint2(pack_bf16(h00, h01), pack_bf16(h10, h11));
            BFL[e] = make_uint2(
                pack_bf16(__float2bfloat16(w00 - __bfloat162float(h00)),
                          __float2bfloat16(w01 - __bfloat162float(h01))),
                pack_bf16(__float2bfloat16(w10 - __bfloat162float(h10)),
                          __float2bfloat16(w11 - __bfloat162float(h11))));
        }
    }
    if (tid < HID) {
        const float* w1g = W1 + (size_t)k * 4 * HID;
        W1Ts[tid] = make_float4(w1g[tid], w1g[HID + tid], w1g[2 * HID + tid], w1g[3 * HID + tid]);
        const float* w3g = W3 + (size_t)k * HID * 3;
        W3Ts[tid] = make_float4(w3g[tid * 3 + 0], w3g[tid * 3 + 1], w3g[tid * 3 + 2], 0.0f);
        b1s[tid] = b1[k * HID + tid];
        b2s[tid] = b2[k * HID + tid];
    }
    if (tid < 3) b3s[tid] = b3[k * 3 + tid];
    __syncthreads();

    // ---- per-thread sample inputs (row tid <-> sample blockIdx.y*128+tid) ----
    const int b_raw = blockIdx.y * 128 + tid;
    const int b = (b_raw < B) ? b_raw : (B - 1);
    const int idx_in = b * NCHAN + k;
    const float tg = tau_g[idx_in];
    const float tl = tau_lw[idx_in];
    const float ti = tau_iw[idx_in];
    const float m  = mu[b];
    const float mb = mu_bar[b];

    if (b_raw < B) {
        const float tau_tot = tg + tl + ti;
        const float t_dir = __expf(-tau_tot / (m + 1e-5f));
        const float t_dif = __expf(-tau_tot / (mb + 1e-3f));
        *reinterpret_cast<float2*>(out + (size_t)idx_in * 8) = make_float2(t_dir, t_dif);
    }

    const int g  = lane >> 2;        // fragment group row 0..7
    const int cq = lane & 3;         // quad col index 0..3

    #pragma unroll 1
    for (int v = 0; v < 2; v++) {
        const float x3 = v ? mb : m;

        // ---- layer 1 for this thread's sample; bf16 split; STS.128 staging ----
        #pragma unroll
        for (int q = 0; q < 8; q++) {          // 8 uint4 per image
            uint32_t whi[4], wlo[4];
            #pragma unroll
            for (int p = 0; p < 4; p++) {
                const int c = q * 4 + p;       // packed word index (cols 2c, 2c+1)
                const float4 wa = W1Ts[2 * c];
                const float4 wb = W1Ts[2 * c + 1];
                float s0 = fmaf(tg, wa.x, b1s[2 * c]);
                s0 = fmaf(tl, wa.y, s0); s0 = fmaf(ti, wa.z, s0); s0 = fmaf(x3, wa.w, s0);
                float s1 = fmaf(tg, wb.x, b1s[2 * c + 1]);
                s1 = fmaf(tl, wb.y, s1); s1 = fmaf(ti, wb.z, s1); s1 = fmaf(x3, wb.w, s1);
                const float h0 = elu_f(s0);
                const float h1 = elu_f(s1);
                const __nv_bfloat16 h0h = __float2bfloat16(h0);
                const __nv_bfloat16 h1h = __float2bfloat16(h1);
                whi[p] = pack_bf16(h0h, h1h);
                wlo[p] = pack_bf16(__float2bfloat16(h0 - __bfloat162float(h0h)),
                                   __float2bfloat16(h1 - __bfloat162float(h1h)));
            }
            reinterpret_cast<uint4*>(&AHI32[tid * 36 + q * 4])[0] =
                make_uint4(whi[0], whi[1], whi[2], whi[3]);
            reinterpret_cast<uint4*>(&ALO32[tid * 36 + q * 4])[0] =
                make_uint4(wlo[0], wlo[1], wlo[2], wlo[3]);
        }
        __syncthreads();

        // ---- mma: warp computes rows [wid*32, wid*32+32), all 64 cols ----
        float acc[2][8][4];
        #pragma unroll
        for (int mt = 0; mt < 2; mt++)
            #pragma unroll
            for (int nt = 0; nt < 8; nt++) {
                const float cA = b2s[nt * 8 + cq * 2];
                const float cB = b2s[nt * 8 + cq * 2 + 1];
                acc[mt][nt][0] = cA; acc[mt][nt][1] = cB;
                acc[mt][nt][2] = cA; acc[mt][nt][3] = cB;
            }

        #pragma unroll
        for (int ks = 0; ks < 4; ks++) {
            uint32_t AH[2][4], AL[2][4];
            #pragma unroll
            for (int mt = 0; mt < 2; mt++) {
                const int r0 = wid * 32 + mt * 16 + g;
                const int w0 = r0 * 36 + ks * 8 + cq;
                const int w1 = (r0 + 8) * 36 + ks * 8 + cq;
                AH[mt][0] = AHI32[w0];     AH[mt][1] = AHI32[w1];
                AH[mt][2] = AHI32[w0 + 4]; AH[mt][3] = AHI32[w1 + 4];
                AL[mt][0] = ALO32[w0];     AL[mt][1] = ALO32[w1];
                AL[mt][2] = ALO32[w0 + 4]; AL[mt][3] = ALO32[w1 + 4];
            }
            #pragma unroll
            for (int nt = 0; nt < 8; nt++) {
                const int e = (ks * 8 + nt) * 32 + lane;
                const uint2 BH = BFH[e];       // one LDS.64, conflict-free
                const uint2 BL = BFL[e];
                #pragma unroll
                for (int mt = 0; mt < 2; mt++) {
                    mma_bf16(acc[mt][nt], AH[mt][0], AH[mt][1], AH[mt][2], AH[mt][3], BH.x, BH.y);
                    mma_bf16(acc[mt][nt], AH[mt][0], AH[mt][1], AH[mt][2], AH[mt][3], BL.x, BL.y);
                    mma_bf16(acc[mt][nt], AL[mt][0], AL[mt][1], AL[mt][2], AL[mt][3], BH.x, BH.y);
                }
            }
        }
        __syncthreads();   // A staging buffers free for next variant

        // ---- epilogue: ELU(h2) . W3, quad reduction, softplus+softmax, direct STG ----
        #pragma unroll
        for (int mt = 0; mt < 2; mt++) {
            float zA0 = 0.f, zA1 = 0.f, zA2 = 0.f;   // row g
            float zB0 = 0.f, zB1 = 0.f, zB2 = 0.f;   // row g+8
            #pragma unroll
            for (int nt = 0; nt < 8; nt++) {
                const int col = nt * 8 + cq * 2;
                const float4 w3a = W3Ts[col];
                const float4 w3b = W3Ts[col + 1];
                const float h00 = elu_f(acc[mt][nt][0]);
                const float h01 = elu_f(acc[mt][nt][1]);
                const float h10 = elu_f(acc[mt][nt][2]);
                const float h11 = elu_f(acc[mt][nt][3]);
                zA0 = fmaf(h00, w3a.x, zA0); zA0 = fmaf(h01, w3b.x, zA0);
                zA1 = fmaf(h00, w3a.y, zA1); zA1 = fmaf(h01, w3b.y, zA1);
                zA2 = fmaf(h00, w3a.z, zA2); zA2 = fmaf(h01, w3b.z, zA2);
                zB0 = fmaf(h10, w3a.x, zB0); zB0 = fmaf(h11, w3b.x, zB0);
                zB1 = fmaf(h10, w3a.y, zB1); zB1 = fmaf(h11, w3b.y, zB1);
                zB2 = fmaf(h10, w3a.z, zB2); zB2 = fmaf(h11, w3b.z, zB2);
            }
            zA0 += __shfl_xor_sync(0xffffffffu, zA0, 1); zA0 += __shfl_xor_sync(0xffffffffu, zA0, 2);
            zA1 += __shfl_xor_sync(0xffffffffu, zA1, 1); zA1 += __shfl_xor_sync(0xffffffffu, zA1, 2);
            zA2 += __shfl_xor_sync(0xffffffffu, zA2, 1); zA2 += __shfl_xor_sync(0xffffffffu, zA2, 2);
            zB0 += __shfl_xor_sync(0xffffffffu, zB0, 1); zB0 += __shfl_xor_sync(0xffffffffu, zB0, 2);
            zB1 += __shfl_xor_sync(0xffffffffu, zB1, 1); zB1 += __shfl_xor_sync(0xffffffffu, zB1, 2);
            zB2 += __shfl_xor_sync(0xffffffffu, zB2, 1); zB2 += __shfl_xor_sync(0xffffffffu, zB2, 2);

            if (cq == 0) {
                const int rowA = wid * 32 + mt * 16 + g;
                #pragma unroll
                for (int h = 0; h < 2; h++) {
                    const float zz0 = h ? zB0 : zA0;
                    const float zz1 = h ? zB1 : zA1;
                    const float zz2 = h ? zB2 : zA2;
                    float z0 = softplus_f(zz0 + b3s[0]);
                    float z1 = softplus_f(zz1 + b3s[1]);
                    float z2 = softplus_f(zz2 + b3s[2]);
                    const float zm = fmaxf(z0, fmaxf(z1, z2));
                    const float e0 = __expf(z0 - zm), e1 = __expf(z1 - zm), e2 = __expf(z2 - zm);
                    const float inv = 1.0f / (e0 + e1 + e2);
                    const int row = rowA + h * 8;
                    const int smp = blockIdx.y * 128 + row;
                    if (smp < B) {
                        float* op = out + ((size_t)smp * NCHAN + k) * 8 + 2 + 3 * v;
                        op[0] = e0 * inv;
                        op[1] = e1 * inv;
                        op[2] = e2 * inv;
                    }
                }
            }
        }
    }
}

extern "C" void kernel_launch(void* const* d_in, const int* in_sizes, int n_in,
                              void* d_out, int out_size) {
    const float* tau_g  = (const float*)d_in[0];
    const float* tau_lw = (const float*)d_in[1];
    const float* tau_iw = (const float*)d_in[2];
    const float* mu     = (const float*)d_in[3];
    const float* mu_bar = (const float*)d_in[4];
    const float* W1     = (const float*)d_in[5];
    const float* b1     = (const float*)d_in[6];
    const float* W2     = (const float*)d_in[7];
    const float* b2     = (const float*)d_in[8];
    const float* W3     = (const float*)d_in[9];
    const float* b3     = (const float*)d_in[10];
    float* out = (float*)d_out;

    const int B = in_sizes[3];  // mu has B elements

    cudaFuncSetAttribute(mlp_kernel, cudaFuncAttributeMaxDynamicSharedMemorySize, SMEM_TOTAL);

    dim3 grid(NCHAN, (B + 127) / 128);
    mlp_kernel<<<grid, 128, SMEM_TOTAL>>>(tau_g, tau_lw, tau_iw, mu, mu_bar,
                                          W1, b1, W2, b2, W3, b3, out, B);
}

// round 11
// speedup vs baseline: 3.1486x; 1.1384x over previous
#include <cuda_runtime.h>
#include <cuda_bf16.h>
#include <cstdint>

// LayerProperties: per-channel 4->64->64->3 MLP x2 variants + epilogue.
// Round 8: single-pass TF32 mma (m16n8k8) replaces the 3-term bf16 split.
//  - deletes all hi/lo split cvt/sub/pack alu (was 40.5% alu pipe)
//  - 128 mma/warp/variant (was 192), single B image, single A image
//  - A row-major fp32 stride 68 (conflict-free LDS/STS), B fragment-order uint2
//  - cvt.rna.tf32 on all MMA inputs for round-to-nearest accuracy

#define NCHAN 29
#define HID   64
#define ASTR  68            // floats per staged A row (bank-conflict-free)

// ---- SMEM byte offsets (dynamic) ----
#define OFF_A    0          // 128 * 68 * 4 = 34816
#define OFF_BF   34816      // [ks=8][nt=8][lane=32] uint2 = 16384
#define OFF_W1T  51200      // float4[64]
#define OFF_W3T  52224      // float4[64]
#define OFF_B1   53248
#define OFF_B2   53504
#define OFF_B3   53760
#define SMEM_TOTAL 53776

__device__ __forceinline__ float elu_f(float x) {
    return x > 0.0f ? x : (__expf(x) - 1.0f);
}
__device__ __forceinline__ float softplus_f(float x) {
    return fmaxf(x, 0.0f) + log1pf(__expf(-fabsf(x)));
}
__device__ __forceinline__ uint32_t to_tf32(float x) {
    uint32_t r;
    asm("cvt.rna.tf32.f32 %0, %1;" : "=r"(r) : "f"(x));
    return r;
}

__device__ __forceinline__ void mma_tf32(float d[4],
                                         uint32_t a0, uint32_t a1, uint32_t a2, uint32_t a3,
                                         uint32_t b0, uint32_t b1) {
    asm volatile(
        "mma.sync.aligned.m16n8k8.row.col.f32.tf32.tf32.f32 "
        "{%0,%1,%2,%3}, {%4,%5,%6,%7}, {%8,%9}, {%0,%1,%2,%3};"
        : "+f"(d[0]), "+f"(d[1]), "+f"(d[2]), "+f"(d[3])
        : "r"(a0), "r"(a1), "r"(a2), "r"(a3), "r"(b0), "r"(b1));
}

__global__ __launch_bounds__(128, 4) void mlp_kernel(
    const float* __restrict__ tau_g,
    const float* __restrict__ tau_lw,
    const float* __restrict__ tau_iw,
    const float* __restrict__ mu,
    const float* __restrict__ mu_bar,
    const float* __restrict__ W1,   // [NC, 4, 64]
    const float* __restrict__ b1,   // [NC, 64]
    const float* __restrict__ W2,   // [NC, 64, 64]  (W2[i][n]: i=input, n=output)
    const float* __restrict__ b2,   // [NC, 64]
    const float* __restrict__ W3,   // [NC, 64, 3]
    const float* __restrict__ b3,   // [NC, 3]
    float* __restrict__ out,        // [B, NC, 8]
    int B)
{
    extern __shared__ __align__(16) unsigned char sm[];
    uint32_t* As  = reinterpret_cast<uint32_t*>(sm + OFF_A);    // [128 rows][68 words] tf32
    uint2* BF     = reinterpret_cast<uint2*>(sm + OFF_BF);
    float4* W1Ts  = reinterpret_cast<float4*>(sm + OFF_W1T);
    float4* W3Ts  = reinterpret_cast<float4*>(sm + OFF_W3T);
    float* b1s    = reinterpret_cast<float*>(sm + OFF_B1);
    float* b2s    = reinterpret_cast<float*>(sm + OFF_B2);
    float* b3s    = reinterpret_cast<float*>(sm + OFF_B3);

    const int tid  = threadIdx.x;
    const int wid  = tid >> 5;
    const int lane = tid & 31;
    const int k    = blockIdx.x;

    // ---- stage B (W2 in tf32, fragment order), once per CTA ----
    // entry e = (ks*8+nt)*32 + lane; b0 = W2[ks*8+cq][n], b1 = W2[ks*8+cq+4][n]
    {
        const float* W2g = W2 + (size_t)k * HID * HID;
        #pragma unroll
        for (int rep = 0; rep < 16; rep++) {
            const int e  = rep * 128 + tid;
            const int el = e & 31;
            const int nt = (e >> 5) & 7;
            const int ks = e >> 8;            // 0..7
            const int g  = el >> 2;
            const int cq = el & 3;
            const int n  = nt * 8 + g;
            BF[e] = make_uint2(to_tf32(W2g[(ks * 8 + cq) * HID + n]),
                               to_tf32(W2g[(ks * 8 + cq + 4) * HID + n]));
        }
    }
    if (tid < HID) {
        const float* w1g = W1 + (size_t)k * 4 * HID;
        W1Ts[tid] = make_float4(w1g[tid], w1g[HID + tid], w1g[2 * HID + tid], w1g[3 * HID + tid]);
        const float* w3g = W3 + (size_t)k * HID * 3;
        W3Ts[tid] = make_float4(w3g[tid * 3 + 0], w3g[tid * 3 + 1], w3g[tid * 3 + 2], 0.0f);
        b1s[tid] = b1[k * HID + tid];
        b2s[tid] = b2[k * HID + tid];
    }
    if (tid < 3) b3s[tid] = b3[k * 3 + tid];
    __syncthreads();

    // ---- per-thread sample inputs (row tid <-> sample blockIdx.y*128+tid) ----
    const int b_raw = blockIdx.y * 128 + tid;
    const int b = (b_raw < B) ? b_raw : (B - 1);
    const int idx_in = b * NCHAN + k;
    const float tg = tau_g[idx_in];
    const float tl = tau_lw[idx_in];
    const float ti = tau_iw[idx_in];
    const float m  = mu[b];
    const float mb = mu_bar[b];

    if (b_raw < B) {
        const float tau_tot = tg + tl + ti;
        const float t_dir = __expf(-tau_tot / (m + 1e-5f));
        const float t_dif = __expf(-tau_tot / (mb + 1e-3f));
        *reinterpret_cast<float2*>(out + (size_t)idx_in * 8) = make_float2(t_dir, t_dif);
    }

    const int g  = lane >> 2;        // fragment group row 0..7
    const int cq = lane & 3;         // quad col index 0..3

    #pragma unroll 1
    for (int v = 0; v < 2; v++) {
        const float x3 = v ? mb : m;

        // ---- layer 1 for this thread's sample -> tf32 -> STS.128 staging ----
        #pragma unroll
        for (int q = 0; q < 16; q++) {         // 16 uint4 per row
            uint32_t w4[4];
            #pragma unroll
            for (int p = 0; p < 4; p++) {
                const int c = q * 4 + p;
                const float4 wa = W1Ts[c];
                float s = fmaf(tg, wa.x, b1s[c]);
                s = fmaf(tl, wa.y, s); s = fmaf(ti, wa.z, s); s = fmaf(x3, wa.w, s);
                w4[p] = to_tf32(elu_f(s));
            }
            reinterpret_cast<uint4*>(&As[tid * ASTR + q * 4])[0] =
                make_uint4(w4[0], w4[1], w4[2], w4[3]);
        }
        __syncthreads();

        // ---- mma: warp computes rows [wid*32, wid*32+32), all 64 cols ----
        float acc[2][8][4];
        #pragma unroll
        for (int mt = 0; mt < 2; mt++)
            #pragma unroll
            for (int nt = 0; nt < 8; nt++) {
                const float cA = b2s[nt * 8 + cq * 2];
                const float cB = b2s[nt * 8 + cq * 2 + 1];
                acc[mt][nt][0] = cA; acc[mt][nt][1] = cB;
                acc[mt][nt][2] = cA; acc[mt][nt][3] = cB;
            }

        #pragma unroll
        for (int ks = 0; ks < 8; ks++) {
            uint32_t A0[2], A1[2], A2[2], A3[2];
            #pragma unroll
            for (int mt = 0; mt < 2; mt++) {
                const int r0 = wid * 32 + mt * 16 + g;
                const int w0 = r0 * ASTR + ks * 8 + cq;
                const int w1 = (r0 + 8) * ASTR + ks * 8 + cq;
                A0[mt] = As[w0];     A1[mt] = As[w1];
                A2[mt] = As[w0 + 4]; A3[mt] = As[w1 + 4];
            }
            #pragma unroll
            for (int nt = 0; nt < 8; nt++) {
                const uint2 Bf = BF[(ks * 8 + nt) * 32 + lane];   // one LDS.64
                #pragma unroll
                for (int mt = 0; mt < 2; mt++)
                    mma_tf32(acc[mt][nt], A0[mt], A1[mt], A2[mt], A3[mt], Bf.x, Bf.y);
            }
        }
        __syncthreads();   // A staging free for next variant

        // ---- epilogue: ELU(h2) . W3, quad reduction, softplus+softmax, direct STG ----
        #pragma unroll
        for (int mt = 0; mt < 2; mt++) {
            float zA0 = 0.f, zA1 = 0.f, zA2 = 0.f;   // row g
            float zB0 = 0.f, zB1 = 0.f, zB2 = 0.f;   // row g+8
            #pragma unroll
            for (int nt = 0; nt < 8; nt++) {
                const int col = nt * 8 + cq * 2;
                const float4 w3a = W3Ts[col];
                const float4 w3b = W3Ts[col + 1];
                const float h00 = elu_f(acc[mt][nt][0]);
                const float h01 = elu_f(acc[mt][nt][1]);
                const float h10 = elu_f(acc[mt][nt][2]);
                const float h11 = elu_f(acc[mt][nt][3]);
                zA0 = fmaf(h00, w3a.x, zA0); zA0 = fmaf(h01, w3b.x, zA0);
                zA1 = fmaf(h00, w3a.y, zA1); zA1 = fmaf(h01, w3b.y, zA1);
                zA2 = fmaf(h00, w3a.z, zA2); zA2 = fmaf(h01, w3b.z, zA2);
                zB0 = fmaf(h10, w3a.x, zB0); zB0 = fmaf(h11, w3b.x, zB0);
                zB1 = fmaf(h10, w3a.y, zB1); zB1 = fmaf(h11, w3b.y, zB1);
                zB2 = fmaf(h10, w3a.z, zB2); zB2 = fmaf(h11, w3b.z, zB2);
            }
            zA0 += __shfl_xor_sync(0xffffffffu, zA0, 1); zA0 += __shfl_xor_sync(0xffffffffu, zA0, 2);
            zA1 += __shfl_xor_sync(0xffffffffu, zA1, 1); zA1 += __shfl_xor_sync(0xffffffffu, zA1, 2);
            zA2 += __shfl_xor_sync(0xffffffffu, zA2, 1); zA2 += __shfl_xor_sync(0xffffffffu, zA2, 2);
            zB0 += __shfl_xor_sync(0xffffffffu, zB0, 1); zB0 += __shfl_xor_sync(0xffffffffu, zB0, 2);
            zB1 += __shfl_xor_sync(0xffffffffu, zB1, 1); zB1 += __shfl_xor_sync(0xffffffffu, zB1, 2);
            zB2 += __shfl_xor_sync(0xffffffffu, zB2, 1); zB2 += __shfl_xor_sync(0xffffffffu, zB2, 2);

            if (cq == 0) {
                const int rowA = wid * 32 + mt * 16 + g;
                #pragma unroll
                for (int h = 0; h < 2; h++) {
                    const float zz0 = h ? zB0 : zA0;
                    const float zz1 = h ? zB1 : zA1;
                    const float zz2 = h ? zB2 : zA2;
                    float z0 = softplus_f(zz0 + b3s[0]);
                    float z1 = softplus_f(zz1 + b3s[1]);
                    float z2 = softplus_f(zz2 + b3s[2]);
                    const float zm = fmaxf(z0, fmaxf(z1, z2));
                    const float e0 = __expf(z0 - zm), e1 = __expf(z1 - zm), e2 = __expf(z2 - zm);
                    const float inv = 1.0f / (e0 + e1 + e2);
                    const int row = rowA + h * 8;
                    const int smp = blockIdx.y * 128 + row;
                    if (smp < B) {
                        float* op = out + ((size_t)smp * NCHAN + k) * 8 + 2 + 3 * v;
                        op[0] = e0 * inv;
                        op[1] = e1 * inv;
                        op[2] = e2 * inv;
                    }
                }
            }
        }
    }
}

extern "C" void kernel_launch(void* const* d_in, const int* in_sizes, int n_in,
                              void* d_out, int out_size) {
    const float* tau_g  = (const float*)d_in[0];
    const float* tau_lw = (const float*)d_in[1];
    const float* tau_iw = (const float*)d_in[2];
    const float* mu     = (const float*)d_in[3];
    const float* mu_bar = (const float*)d_in[4];
    const float* W1     = (const float*)d_in[5];
    const float* b1     = (const float*)d_in[6];
    const float* W2     = (const float*)d_in[7];
    const float* b2     = (const float*)d_in[8];
    const float* W3     = (const float*)d_in[9];
    const float* b3     = (const float*)d_in[10];
    float* out = (float*)d_out;

    const int B = in_sizes[3];  // mu has B elements

    cudaFuncSetAttribute(mlp_kernel, cudaFuncAttributeMaxDynamicSharedMemorySize, SMEM_TOTAL);

    dim3 grid(NCHAN, (B + 127) / 128);
    mlp_kernel<<<grid, 128, SMEM_TOTAL>>>(tau_g, tau_lw, tau_iw, mu, mu_bar,
                                          W1, b1, W2, b2, W3, b3, out, B);
}

// round 12
// speedup vs baseline: 4.2236x; 1.3414x over previous
#include <cuda_runtime.h>
#include <cuda_bf16.h>
#include <cstdint>

// LayerProperties: per-channel 4->64->64->3 MLP x2 variants + epilogue.
// Round 11: A fragments computed DIRECTLY in registers (layer-1 is only 4 FFMA/value),
// deleting the SMEM staging round-trip (STS/LDS/cvt) and ALL mainloop barriers.
//  - inputs of the CTA's 128 samples staged once; each thread reads its 4 source rows
//  - per (variant, ks): 8 A values = 2 LDS.128 (W1 cols) + 32 FFMA + 8 ELU -> mma
//  - A passed as raw fp32 bits (HW tf32 truncation); B cvt.rna once per CTA
//  - smem ~21.5 KB static; tf32 m16n8k8 mma, 128/warp/variant

#define NCHAN 29
#define HID   64

__device__ __forceinline__ float elu_f(float x) {
    return x > 0.0f ? x : (__expf(x) - 1.0f);
}
__device__ __forceinline__ float softplus_f(float x) {
    return fmaxf(x, 0.0f) + log1pf(__expf(-fabsf(x)));
}
__device__ __forceinline__ uint32_t to_tf32(float x) {
    uint32_t r;
    asm("cvt.rna.tf32.f32 %0, %1;" : "=r"(r) : "f"(x));
    return r;
}

__device__ __forceinline__ void mma_tf32(float d[4],
                                         uint32_t a0, uint32_t a1, uint32_t a2, uint32_t a3,
                                         uint32_t b0, uint32_t b1) {
    asm volatile(
        "mma.sync.aligned.m16n8k8.row.col.f32.tf32.tf32.f32 "
        "{%0,%1,%2,%3}, {%4,%5,%6,%7}, {%8,%9}, {%0,%1,%2,%3};"
        : "+f"(d[0]), "+f"(d[1]), "+f"(d[2]), "+f"(d[3])
        : "r"(a0), "r"(a1), "r"(a2), "r"(a3), "r"(b0), "r"(b1));
}

__global__ __launch_bounds__(128, 4) void mlp_kernel(
    const float* __restrict__ tau_g,
    const float* __restrict__ tau_lw,
    const float* __restrict__ tau_iw,
    const float* __restrict__ mu,
    const float* __restrict__ mu_bar,
    const float* __restrict__ W1,   // [NC, 4, 64]
    const float* __restrict__ b1,   // [NC, 64]
    const float* __restrict__ W2,   // [NC, 64, 64]  (W2[i][n]: i=input, n=output)
    const float* __restrict__ b2,   // [NC, 64]
    const float* __restrict__ W3,   // [NC, 64, 3]
    const float* __restrict__ b3,   // [NC, 3]
    float* __restrict__ out,        // [B, NC, 8]
    int B)
{
    __shared__ uint2  BF[2048];          // [ks=8][nt=8][lane=32], 16 KB
    __shared__ float4 W1Ts[HID];         // col-major W1: (W1[0][c],W1[1][c],W1[2][c],W1[3][c])
    __shared__ float4 W3Ts[HID];         // (W3[c][0..2], 0)
    __shared__ float  b1s[HID], b2s[HID], b3s[3];
    __shared__ float  inTG[128], inTL[128], inTI[128], inM[128], inMB[128];

    const int tid  = threadIdx.x;
    const int wid  = tid >> 5;
    const int lane = tid & 31;
    const int k    = blockIdx.x;

    // ---- stage B (W2 in tf32, fragment order), once per CTA ----
    {
        const float* W2g = W2 + (size_t)k * HID * HID;
        #pragma unroll
        for (int rep = 0; rep < 16; rep++) {
            const int e  = rep * 128 + tid;
            const int el = e & 31;
            const int nt = (e >> 5) & 7;
            const int ks = e >> 8;            // 0..7
            const int gg = el >> 2;
            const int cc = el & 3;
            const int n  = nt * 8 + gg;
            BF[e] = make_uint2(to_tf32(W2g[(ks * 8 + cc) * HID + n]),
                               to_tf32(W2g[(ks * 8 + cc + 4) * HID + n]));
        }
    }
    if (tid < HID) {
        const float* w1g = W1 + (size_t)k * 4 * HID;
        W1Ts[tid] = make_float4(w1g[tid], w1g[HID + tid], w1g[2 * HID + tid], w1g[3 * HID + tid]);
        const float* w3g = W3 + (size_t)k * HID * 3;
        W3Ts[tid] = make_float4(w3g[tid * 3 + 0], w3g[tid * 3 + 1], w3g[tid * 3 + 2], 0.0f);
        b1s[tid] = b1[k * HID + tid];
        b2s[tid] = b2[k * HID + tid];
    }
    if (tid < 3) b3s[tid] = b3[k * 3 + tid];

    // ---- stage this CTA's 128 samples' inputs + write transmittances ----
    const int b_raw = blockIdx.y * 128 + tid;
    {
        const int b = (b_raw < B) ? b_raw : (B - 1);
        const int idx_in = b * NCHAN + k;
        const float tg = tau_g[idx_in];
        const float tl = tau_lw[idx_in];
        const float ti = tau_iw[idx_in];
        const float m  = mu[b];
        const float mb = mu_bar[b];
        inTG[tid] = tg; inTL[tid] = tl; inTI[tid] = ti; inM[tid] = m; inMB[tid] = mb;
        if (b_raw < B) {
            const float tau_tot = tg + tl + ti;
            const float t_dir = __expf(-tau_tot / (m + 1e-5f));
            const float t_dif = __expf(-tau_tot / (mb + 1e-3f));
            *reinterpret_cast<float2*>(out + (size_t)idx_in * 8) = make_float2(t_dir, t_dif);
        }
    }
    __syncthreads();   // the ONLY barrier

    const int g  = lane >> 2;        // fragment group row 0..7
    const int cq = lane & 3;         // quad col index 0..3

    // ---- pull the 4 source rows' inputs into registers ----
    float rtg[4], rtl[4], rti[4], rm[4], rmb[4];
    #pragma unroll
    for (int j = 0; j < 4; j++) {
        const int r = wid * 32 + g + 8 * j;
        rtg[j] = inTG[r]; rtl[j] = inTL[r]; rti[j] = inTI[r];
        rm[j] = inM[r];   rmb[j] = inMB[r];
    }

    #pragma unroll 1
    for (int v = 0; v < 2; v++) {
        float rx3[4];
        #pragma unroll
        for (int j = 0; j < 4; j++) rx3[j] = v ? rmb[j] : rm[j];

        // ---- acc init from b2 ----
        float acc[2][8][4];
        #pragma unroll
        for (int mt = 0; mt < 2; mt++)
            #pragma unroll
            for (int nt = 0; nt < 8; nt++) {
                const float cA = b2s[nt * 8 + cq * 2];
                const float cB = b2s[nt * 8 + cq * 2 + 1];
                acc[mt][nt][0] = cA; acc[mt][nt][1] = cB;
                acc[mt][nt][2] = cA; acc[mt][nt][3] = cB;
            }

        // ---- mainloop: A fragments computed in place, no staging, no barriers ----
        #pragma unroll
        for (int ks = 0; ks < 8; ks++) {
            const int c0 = ks * 8 + cq;
            const int c1 = c0 + 4;
            const float4 w0 = W1Ts[c0];
            const float4 w1c = W1Ts[c1];
            const float bb0 = b1s[c0];
            const float bb1 = b1s[c1];
            uint32_t af0[4], af1[4];
            #pragma unroll
            for (int j = 0; j < 4; j++) {
                float s0 = fmaf(rtg[j], w0.x, bb0);
                s0 = fmaf(rtl[j], w0.y, s0);
                s0 = fmaf(rti[j], w0.z, s0);
                s0 = fmaf(rx3[j], w0.w, s0);
                af0[j] = __float_as_uint(elu_f(s0));
                float s1 = fmaf(rtg[j], w1c.x, bb1);
                s1 = fmaf(rtl[j], w1c.y, s1);
                s1 = fmaf(rti[j], w1c.z, s1);
                s1 = fmaf(rx3[j], w1c.w, s1);
                af1[j] = __float_as_uint(elu_f(s1));
            }
            #pragma unroll
            for (int nt = 0; nt < 8; nt++) {
                const uint2 Bf = BF[(ks * 8 + nt) * 32 + lane];   // one LDS.64
                mma_tf32(acc[0][nt], af0[0], af0[1], af1[0], af1[1], Bf.x, Bf.y);
                mma_tf32(acc[1][nt], af0[2], af0[3], af1[2], af1[3], Bf.x, Bf.y);
            }
        }

        // ---- epilogue: ELU(h2) . W3, quad reduction, softplus+softmax, direct STG ----
        #pragma unroll
        for (int mt = 0; mt < 2; mt++) {
            float zA0 = 0.f, zA1 = 0.f, zA2 = 0.f;   // row g      (j = 2*mt)
            float zB0 = 0.f, zB1 = 0.f, zB2 = 0.f;   // row g+8    (j = 2*mt+1)
            #pragma unroll
            for (int nt = 0; nt < 8; nt++) {
                const int col = nt * 8 + cq * 2;
                const float4 w3a = W3Ts[col];
                const float4 w3b = W3Ts[col + 1];
                const float h00 = elu_f(acc[mt][nt][0]);
                const float h01 = elu_f(acc[mt][nt][1]);
                const float h10 = elu_f(acc[mt][nt][2]);
                const float h11 = elu_f(acc[mt][nt][3]);
                zA0 = fmaf(h00, w3a.x, zA0); zA0 = fmaf(h01, w3b.x, zA0);
                zA1 = fmaf(h00, w3a.y, zA1); zA1 = fmaf(h01, w3b.y, zA1);
                zA2 = fmaf(h00, w3a.z, zA2); zA2 = fmaf(h01, w3b.z, zA2);
                zB0 = fmaf(h10, w3a.x, zB0); zB0 = fmaf(h11, w3b.x, zB0);
                zB1 = fmaf(h10, w3a.y, zB1); zB1 = fmaf(h11, w3b.y, zB1);
                zB2 = fmaf(h10, w3a.z, zB2); zB2 = fmaf(h11, w3b.z, zB2);
            }
            zA0 += __shfl_xor_sync(0xffffffffu, zA0, 1); zA0 += __shfl_xor_sync(0xffffffffu, zA0, 2);
            zA1 += __shfl_xor_sync(0xffffffffu, zA1, 1); zA1 += __shfl_xor_sync(0xffffffffu, zA1, 2);
            zA2 += __shfl_xor_sync(0xffffffffu, zA2, 1); zA2 += __shfl_xor_sync(0xffffffffu, zA2, 2);
            zB0 += __shfl_xor_sync(0xffffffffu, zB0, 1); zB0 += __shfl_xor_sync(0xffffffffu, zB0, 2);
            zB1 += __shfl_xor_sync(0xffffffffu, zB1, 1); zB1 += __shfl_xor_sync(0xffffffffu, zB1, 2);
            zB2 += __shfl_xor_sync(0xffffffffu, zB2, 1); zB2 += __shfl_xor_sync(0xffffffffu, zB2, 2);

            if (cq == 0) {
                const int rowA = wid * 32 + mt * 16 + g;
                #pragma unroll
                for (int h = 0; h < 2; h++) {
                    const float zz0 = h ? zB0 : zA0;
                    const float zz1 = h ? zB1 : zA1;
                    const float zz2 = h ? zB2 : zA2;
                    float z0 = softplus_f(zz0 + b3s[0]);
                    float z1 = softplus_f(zz1 + b3s[1]);
                    float z2 = softplus_f(zz2 + b3s[2]);
                    const float zm = fmaxf(z0, fmaxf(z1, z2));
                    const float e0 = __expf(z0 - zm), e1 = __expf(z1 - zm), e2 = __expf(z2 - zm);
                    const float inv = 1.0f / (e0 + e1 + e2);
                    const int row = rowA + h * 8;
                    const int smp = blockIdx.y * 128 + row;
                    if (smp < B) {
                        float* op = out + ((size_t)smp * NCHAN + k) * 8 + 2 + 3 * v;
                        op[0] = e0 * inv;
                        op[1] = e1 * inv;
                        op[2] = e2 * inv;
                    }
                }
            }
        }
    }
}

extern "C" void kernel_launch(void* const* d_in, const int* in_sizes, int n_in,
                              void* d_out, int out_size) {
    const float* tau_g  = (const float*)d_in[0];
    const float* tau_lw = (const float*)d_in[1];
    const float* tau_iw = (const float*)d_in[2];
    const float* mu     = (const float*)d_in[3];
    const float* mu_bar = (const float*)d_in[4];
    const float* W1     = (const float*)d_in[5];
    const float* b1     = (const float*)d_in[6];
    const float* W2     = (const float*)d_in[7];
    const float* b2     = (const float*)d_in[8];
    const float* W3     = (const float*)d_in[9];
    const float* b3     = (const float*)d_in[10];
    float* out = (float*)d_out;

    const int B = in_sizes[3];  // mu has B elements

    dim3 grid(NCHAN, (B + 127) / 128);
    mlp_kernel<<<grid, 128>>>(tau_g, tau_lw, tau_iw, mu, mu_bar,
                              W1, b1, W2, b2, W3, b3, out, B);
}